// round 13
// baseline (speedup 1.0000x reference)
#include <cuda_runtime.h>
#include <math_constants.h>
#include <cstdint>

#define C        32000
#define C4       (C / 4)            // 8000 float4 per row
#define GRID_PTS 100
#define NMIDS    (GRID_PTS - 1)
#define THREADS  1024
#define NWARP    (THREADS / 32)     // 32

__global__ __launch_bounds__(THREADS, 2)
void calib_kernel(const float* __restrict__ logits,
                  const float* __restrict__ log_temp,
                  const float* __restrict__ iso_x,
                  const float* __restrict__ iso_y,
                  float* __restrict__ out,
                  int rows, int nblk)
{
    __shared__ float thr[NMIDS];        // log-domain thresholds for current row
    __shared__ float ybuf[GRID_PTS];
    __shared__ float redm[NWARP];
    __shared__ float reds[NWARP];
    __shared__ float fin[2];            // M, S

    const int tid  = threadIdx.x;
    const int lane = tid & 31;
    const int wid  = tid >> 5;

    int row = blockIdx.x;
    if (row >= rows) return;

    // temperature = clamp(exp(log_T), 0.1, 10); fold log2(e)/T into the scale
    const float T  = fminf(fmaxf(expf(log_temp[0]), 0.1f), 10.0f);
    const float s2 = 1.4426950408889634f / T;   // base-2 scale

    if (tid < GRID_PTS) ybuf[tid] = iso_y[tid];

    // --- helper: block-combine (m,s), then write thresholds for that row ---
    // thr[i] = log2(mids[i]*S) + M   (mids[i]*S < 2^(x-M)  <=>  thr[i] < x)
    auto reduce_and_thresholds = [&](float m, float s) {
        #pragma unroll
        for (int o = 16; o; o >>= 1) {
            float mo = __shfl_xor_sync(0xffffffffu, m, o);
            float so = __shfl_xor_sync(0xffffffffu, s, o);
            float nm = fmaxf(m, mo);
            s = s * exp2f(m - nm) + so * exp2f(mo - nm);
            m = nm;
        }
        if (lane == 0) { redm[wid] = m; reds[wid] = s; }
        __syncthreads();
        if (wid == 0) {
            float mm = redm[lane];          // NWARP == 32: every lane valid
            float ss = reds[lane];
            #pragma unroll
            for (int o = 16; o; o >>= 1) {
                float mo = __shfl_xor_sync(0xffffffffu, mm, o);
                float so = __shfl_xor_sync(0xffffffffu, ss, o);
                float nm = fmaxf(mm, mo);
                ss = ss * exp2f(mm - nm) + so * exp2f(mo - nm);
                mm = nm;
            }
            if (lane == 0) { fin[0] = mm; fin[1] = ss; }
        }
        __syncthreads();
        const float M = fin[0];
        const float S = fin[1];
        if (tid < NMIDS)
            thr[tid] = log2f(0.5f * (iso_x[tid] + iso_x[tid + 1]) * S) + M;
        __syncthreads();
    };

    // ---- prologue: stream first row from HBM with fused online (m,s) ----
    const float4* cur = reinterpret_cast<const float4*>(logits + (long long)row * C);
    {
        float m = -CUDART_INF_F, s = 0.0f;
        #pragma unroll 2
        for (int i = tid; i < C4; i += THREADS) {
            float4 v = cur[i];
            v.x *= s2; v.y *= s2; v.z *= s2; v.w *= s2;
            float mx = fmaxf(fmaxf(v.x, v.y), fmaxf(v.z, v.w));
            if (mx > m) { s *= exp2f(m - mx); m = mx; }   // rare rescale
            s += (exp2f(v.x - m) + exp2f(v.y - m)) + (exp2f(v.z - m) + exp2f(v.w - m));
        }
        reduce_and_thresholds(m, s);
    }

    // ---- steady state: write row r (L2 re-read + bin) while reading row r+nblk ----
    for (;;) {
        const int  next_row = row + nblk;
        const bool has_next = next_row < rows;
        const float4* nxt = has_next
            ? reinterpret_cast<const float4*>(logits + (long long)next_row * C)
            : cur;
        float4* o4 = reinterpret_cast<float4*>(out + (long long)row * C);

        const float L0 = thr[0];
        const float y0 = ybuf[0];
        float m = -CUDART_INF_F, s = 0.0f;

        #pragma unroll 2
        for (int i = tid; i < C4; i += THREADS) {
            // read next row (DRAM) + online softmax
            if (has_next) {
                float4 v = nxt[i];
                v.x *= s2; v.y *= s2; v.z *= s2; v.w *= s2;
                float mx = fmaxf(fmaxf(v.x, v.y), fmaxf(v.z, v.w));
                if (mx > m) { s *= exp2f(m - mx); m = mx; }
                s += (exp2f(v.x - m) + exp2f(v.y - m)) + (exp2f(v.z - m) + exp2f(v.w - m));
            }
            // re-read current row (L2-resident), bin, write (DRAM)
            float4 v = cur[i];
            v.x *= s2; v.y *= s2; v.z *= s2; v.w *= s2;   // bit-identical to its read pass
            float4 r;
            float* vp = &v.x;
            float* rp = &r.x;
            #pragma unroll
            for (int k = 0; k < 4; k++) {
                float xv = vp[k];
                if (xv <= L0) {
                    rp[k] = y0;               // warp-uniform fast path (~all of a softmax row)
                } else {
                    int lo = 1, hi = NMIDS;   // thr[0] < xv already established
                    while (lo < hi) {
                        int mid = (lo + hi) >> 1;
                        if (thr[mid] < xv) lo = mid + 1; else hi = mid;
                    }
                    rp[k] = ybuf[lo];
                }
            }
            o4[i] = r;
        }

        if (!has_next) break;
        __syncthreads();                    // all reads of old thr done before overwrite
        reduce_and_thresholds(m, s);        // thresholds for next_row
        row = next_row;
        cur = nxt;
    }
}

extern "C" void kernel_launch(void* const* d_in, const int* in_sizes, int n_in,
                              void* d_out, int out_size) {
    const float* logits   = (const float*)d_in[0];
    const float* log_temp = (const float*)d_in[1];
    const float* iso_x    = (const float*)d_in[2];
    const float* iso_y    = (const float*)d_in[3];
    float* out = (float*)d_out;

    const int rows = out_size / C;
    int nblk = 2 * 148;                 // 2 persistent CTAs per SM
    if (nblk > rows) nblk = rows;

    calib_kernel<<<nblk, THREADS>>>(logits, log_temp, iso_x, iso_y, out, rows, nblk);
}

// round 14
// speedup vs baseline: 1.0061x; 1.0061x over previous
#include <cuda_runtime.h>
#include <math_constants.h>
#include <cstdint>

#define C        32000
#define C4       (C / 4)            // 8000 float4 per row
#define GRID_PTS 100
#define NMIDS    (GRID_PTS - 1)
#define THREADS  1024
#define NWARP    (THREADS / 32)     // 32
#define CHUNKS   8                  // ceil(C4 / THREADS)

__global__ __launch_bounds__(THREADS, 1)
void calib_kernel(const float* __restrict__ logits,
                  const float* __restrict__ log_temp,
                  const float* __restrict__ iso_x,
                  const float* __restrict__ iso_y,
                  float* __restrict__ out,
                  int rows, int nblk)
{
    __shared__ float thr[NMIDS];        // log-domain thresholds for current row
    __shared__ float ybuf[GRID_PTS];
    __shared__ float redm[NWARP];
    __shared__ float reds[NWARP];
    __shared__ float fin[2];            // M, S

    const int tid  = threadIdx.x;
    const int lane = tid & 31;
    const int wid  = tid >> 5;

    int row = blockIdx.x;
    if (row >= rows) return;

    // temperature = clamp(exp(log_T), 0.1, 10); fold log2(e)/T into the scale
    const float T  = fminf(fmaxf(expf(log_temp[0]), 0.1f), 10.0f);
    const float s2 = 1.4426950408889634f / T;   // base-2 scale

    if (tid < GRID_PTS) ybuf[tid] = iso_y[tid];

    // --- block-combine (m,s), then thresholds for that row ---
    // thr[i] = log2(mids[i]*S) + M   (mids[i]*S < 2^(x-M)  <=>  thr[i] < x)
    auto reduce_and_thresholds = [&](float m, float s) {
        #pragma unroll
        for (int o = 16; o; o >>= 1) {
            float mo = __shfl_xor_sync(0xffffffffu, m, o);
            float so = __shfl_xor_sync(0xffffffffu, s, o);
            float nm = fmaxf(m, mo);
            s = s * exp2f(m - nm) + so * exp2f(mo - nm);
            m = nm;
        }
        if (lane == 0) { redm[wid] = m; reds[wid] = s; }
        __syncthreads();
        if (wid == 0) {
            float mm = redm[lane];          // NWARP == 32: every lane valid
            float ss = reds[lane];
            #pragma unroll
            for (int o = 16; o; o >>= 1) {
                float mo = __shfl_xor_sync(0xffffffffu, mm, o);
                float so = __shfl_xor_sync(0xffffffffu, ss, o);
                float nm = fmaxf(mm, mo);
                ss = ss * exp2f(mm - nm) + so * exp2f(mo - nm);
                mm = nm;
            }
            if (lane == 0) { fin[0] = mm; fin[1] = ss; }
        }
        __syncthreads();
        const float M = fin[0];
        const float S = fin[1];
        if (tid < NMIDS)
            thr[tid] = log2f(0.5f * (iso_x[tid] + iso_x[tid + 1]) * S) + M;
        __syncthreads();
    };

    float4 cur[CHUNKS];                 // current row, register-resident (scaled)

    // ---- prologue: stream first row from HBM into registers, fused (m,s) ----
    {
        const float4* p = reinterpret_cast<const float4*>(logits + (long long)row * C);
        float m = -CUDART_INF_F, s = 0.0f;
        #pragma unroll
        for (int k = 0; k < CHUNKS; k++) {
            const int idx = tid + k * THREADS;
            if (idx < C4) {
                float4 v = p[idx];
                v.x *= s2; v.y *= s2; v.z *= s2; v.w *= s2;
                cur[k] = v;
                float mx = fmaxf(fmaxf(v.x, v.y), fmaxf(v.z, v.w));
                if (mx > m) { s *= exp2f(m - mx); m = mx; }   // rare rescale
                s += (exp2f(v.x - m) + exp2f(v.y - m)) + (exp2f(v.z - m) + exp2f(v.w - m));
            }
        }
        reduce_and_thresholds(m, s);
    }

    // ---- steady state: write row r from registers while reading row r+nblk ----
    for (;;) {
        const int  next_row = row + nblk;
        const bool has_next = next_row < rows;
        const float4* np = reinterpret_cast<const float4*>(logits + (long long)next_row * C);
        float4* o4 = reinterpret_cast<float4*>(out + (long long)row * C);

        const float L0 = thr[0];
        const float y0 = ybuf[0];
        float m = -CUDART_INF_F, s = 0.0f;

        #pragma unroll
        for (int k = 0; k < CHUNKS; k++) {
            const int idx = tid + k * THREADS;
            const bool ok = idx < C4;
            float4 v;
            if (has_next & ok) {
                v = np[idx];                               // DRAM read (next row)
                v.x *= s2; v.y *= s2; v.z *= s2; v.w *= s2;
                float mx = fmaxf(fmaxf(v.x, v.y), fmaxf(v.z, v.w));
                if (mx > m) { s *= exp2f(m - mx); m = mx; }
                s += (exp2f(v.x - m) + exp2f(v.y - m)) + (exp2f(v.z - m) + exp2f(v.w - m));
            }
            if (ok) {
                float4 c = cur[k];
                float4 r;
                float* cp = &c.x;
                float* rp = &r.x;
                #pragma unroll
                for (int j = 0; j < 4; j++) {
                    float xv = cp[j];
                    if (xv <= L0) {
                        rp[j] = y0;               // warp-uniform fast path
                    } else {
                        int lo = 1, hi = NMIDS;   // thr[0] < xv already established
                        while (lo < hi) {
                            int mid = (lo + hi) >> 1;
                            if (thr[mid] < xv) lo = mid + 1; else hi = mid;
                        }
                        rp[j] = ybuf[lo];
                    }
                }
                o4[idx] = r;                               // DRAM write (current row)
            }
            if (has_next & ok) cur[k] = v;                 // rotate
        }

        if (!has_next) break;
        __syncthreads();                    // old thr fully consumed before overwrite
        reduce_and_thresholds(m, s);        // thresholds for next_row
        row = next_row;
    }
}

extern "C" void kernel_launch(void* const* d_in, const int* in_sizes, int n_in,
                              void* d_out, int out_size) {
    const float* logits   = (const float*)d_in[0];
    const float* log_temp = (const float*)d_in[1];
    const float* iso_x    = (const float*)d_in[2];
    const float* iso_y    = (const float*)d_in[3];
    float* out = (float*)d_out;

    const int rows = out_size / C;
    int nblk = 148;                     // 1 persistent CTA per SM (register-resident row)
    if (nblk > rows) nblk = rows;

    calib_kernel<<<nblk, THREADS>>>(logits, log_temp, iso_x, iso_y, out, rows, nblk);
}